// round 14
// baseline (speedup 1.0000x reference)
#include <cuda_runtime.h>
#include <cuda_fp16.h>
#include <mma.h>
#include <math.h>
#include <stdint.h>

using namespace nvcuda;

#define N_NODES  100000
#define N_EDGES  3200000
#define N_GRAPHS 512
#define F_IN     128
#define F_HID    64
#define F_OUT    10

#define SCAN_B   512
#define NBLK     ((N_NODES + SCAN_B - 1) / SCAN_B)   // 196

#define TG_GRID  1184

// ---------------- scratch (device globals: no allocation allowed) ----------
__device__ int     g_count [N_NODES];
__device__ int     g_cursor[N_NODES];
__device__ int     g_off   [N_NODES + 1];
__device__ int     g_bsum  [NBLK];
__device__ int     g_boff  [NBLK];
__device__ int     g_src   [N_EDGES];
__device__ float   g_dinv  [N_NODES];
__device__ __half2 g_h2    [N_NODES * 32];   // messages, fp16, pre-scaled
__device__ __half2 g_xh1   [N_NODES * 32];   // activations, fp16
__device__ __half2 g_xh2   [N_NODES * 32];
__device__ __half2 g_xh3   [N_NODES * 32];
__device__ int     g_start [N_GRAPHS + 1];
__device__ float   g_pool  [N_GRAPHS * 3 * F_HID];

// ---------------- prep -------------------------------------------------------
__global__ void init_kernel() {
    int i = blockIdx.x * blockDim.x + threadIdx.x;
    int stride = gridDim.x * blockDim.x;
    for (int k = i; k < N_NODES; k += stride) g_count[k] = 0;
    for (int k = i; k <= N_GRAPHS; k += stride) g_start[k] = -1;
}

__global__ void count_kernel(const int* __restrict__ ei) {
    int t = blockIdx.x * blockDim.x + threadIdx.x;
    if (t >= N_EDGES / 4) return;
    int4 c = __ldg(&((const int4*)(ei + N_EDGES))[t]);
    if ((unsigned)c.x < N_NODES) atomicAdd(&g_count[c.x], 1);
    if ((unsigned)c.y < N_NODES) atomicAdd(&g_count[c.y], 1);
    if ((unsigned)c.z < N_NODES) atomicAdd(&g_count[c.z], 1);
    if ((unsigned)c.w < N_NODES) atomicAdd(&g_count[c.w], 1);
}

__global__ void scan1_kernel() {
    __shared__ int s[SCAN_B];
    int t = threadIdx.x;
    int i = blockIdx.x * SCAN_B + t;
    int v = (i < N_NODES) ? g_count[i] : 0;
    if (i < N_NODES) g_dinv[i] = (v > 0) ? rsqrtf((float)v) : 0.0f;
    s[t] = v; __syncthreads();
    int x = v;
    for (int o = 1; o < SCAN_B; o <<= 1) {
        int y = (t >= o) ? s[t - o] : 0;
        __syncthreads();
        x += y; s[t] = x;
        __syncthreads();
    }
    if (i < N_NODES) g_off[i] = x - v;
    if (t == SCAN_B - 1) g_bsum[blockIdx.x] = x;
}

__global__ void scan2_kernel() {
    __shared__ int s[256];
    int t = threadIdx.x;
    int v = (t < NBLK) ? g_bsum[t] : 0;
    s[t] = v; __syncthreads();
    int x = v;
    for (int o = 1; o < 256; o <<= 1) {
        int y = (t >= o) ? s[t - o] : 0;
        __syncthreads();
        x += y; s[t] = x;
        __syncthreads();
    }
    if (t < NBLK) g_boff[t] = x - v;
}

__global__ void scan3_kernel() {
    int i = blockIdx.x * blockDim.x + threadIdx.x;
    if (i < N_NODES) {
        int off = g_off[i] + g_boff[i / SCAN_B];
        g_off[i] = off;
        g_cursor[i] = off;                 // prime scatter cursors
    }
    if (i == 0) g_off[N_NODES] = N_EDGES;
}

__global__ void scatter_kernel(const int* __restrict__ ei) {
    int t = blockIdx.x * blockDim.x + threadIdx.x;
    if (t >= N_EDGES / 4) return;
    int4 r = __ldg(&((const int4*)ei)[t]);
    int4 c = __ldg(&((const int4*)(ei + N_EDGES))[t]);
    if ((unsigned)c.x < N_NODES) g_src[atomicAdd(&g_cursor[c.x], 1)] = r.x;
    if ((unsigned)c.y < N_NODES) g_src[atomicAdd(&g_cursor[c.y], 1)] = r.y;
    if ((unsigned)c.z < N_NODES) g_src[atomicAdd(&g_cursor[c.z], 1)] = r.z;
    if ((unsigned)c.w < N_NODES) g_src[atomicAdd(&g_cursor[c.w], 1)] = r.w;
}

// ------- GEMM via wmma (HMMA): h2[n] = half2( (X[n,:K] @ W) * dinv[n] ) -----
// 128 threads = 4 warps; tile = 64 nodes (16/warp). fp16 in, fp32 accum.
// A: X tile row-major [64, K] in smem. B: W row-major [K, 64] in smem.
// Out staged f32 in smem (reusing the X buffer), fused dinv scale + fp16 pack.
template <int K>
__global__ __launch_bounds__(128) void tgemm_kernel(
        const float* __restrict__ Xext, const float* __restrict__ W, int src) {
    constexpr int XB = 64 * K * 2;                 // X tile bytes (fp16)
    constexpr int BUF = (XB > 16384) ? XB : 16384; // also holds 64x64 f32 out
    __shared__ __half        sW[K * 64];
    __shared__ unsigned char sbuf[BUF];
    __half* sX   = (__half*)sbuf;
    float*  sOut = (float*)sbuf;

    int tid = threadIdx.x, warp = tid >> 5;

    // stage W (K x 64) once, coalesced
    for (int i = tid; i < K * 64; i += 128)
        sW[i] = __float2half_rn(__ldg(&W[i]));

    const __half2* Xh = (src == 1) ? g_xh1 : g_xh2;
    const int NT = (N_NODES + 63) / 64;            // 1563
    for (int tile = blockIdx.x; tile < NT; tile += gridDim.x) {
        int node0 = tile * 64;
        __syncthreads();                            // sW ready / sbuf reusable
        if (src == 0) {
            for (int i = tid; i < 64 * K / 8; i += 128) {
                int row = i / (K / 8), c8 = i % (K / 8);
                int node = node0 + row;
                uint4 out = make_uint4(0, 0, 0, 0);
                if (node < N_NODES) {
                    const float4* xp =
                        (const float4*)(Xext + (size_t)node * K + c8 * 8);
                    float4 u = __ldg(xp), v = __ldg(xp + 1);
                    __half2 p0 = __floats2half2_rn(u.x, u.y);
                    __half2 p1 = __floats2half2_rn(u.z, u.w);
                    __half2 p2 = __floats2half2_rn(v.x, v.y);
                    __half2 p3 = __floats2half2_rn(v.z, v.w);
                    out.x = *(uint32_t*)&p0; out.y = *(uint32_t*)&p1;
                    out.z = *(uint32_t*)&p2; out.w = *(uint32_t*)&p3;
                }
                ((uint4*)sX)[i] = out;
            }
        } else {
            for (int i = tid; i < 64 * (K / 8); i += 128) {
                int row = i / (K / 8), c16 = i % (K / 8);
                int node = node0 + row;
                uint4 val = make_uint4(0, 0, 0, 0);
                if (node < N_NODES)
                    val = ((const uint4*)&Xh[(size_t)node * 32])[c16];
                ((uint4*)sX)[i] = val;
            }
        }
        __syncthreads();

        wmma::fragment<wmma::accumulator, 16, 16, 16, float> acc[4];
#pragma unroll
        for (int j = 0; j < 4; j++) wmma::fill_fragment(acc[j], 0.0f);
        wmma::fragment<wmma::matrix_a, 16, 16, 16, __half, wmma::row_major> a;
        wmma::fragment<wmma::matrix_b, 16, 16, 16, __half, wmma::row_major> b;
        int rowBase = warp * 16;
#pragma unroll
        for (int ks = 0; ks < K / 16; ks++) {
            wmma::load_matrix_sync(a, &sX[rowBase * K + ks * 16], K);
#pragma unroll
            for (int j = 0; j < 4; j++) {
                wmma::load_matrix_sync(b, &sW[ks * 16 * 64 + j * 16], 64);
                wmma::mma_sync(acc[j], a, b, acc[j]);
            }
        }
        __syncthreads();                            // sX reads done
#pragma unroll
        for (int j = 0; j < 4; j++)
            wmma::store_matrix_sync(&sOut[rowBase * 64 + j * 16], acc[j], 64,
                                    wmma::mem_row_major);
        __syncthreads();

        // fused dinv scale + fp16 pack; 2 threads per row
        int row = tid >> 1, hsel = tid & 1;
        int node = node0 + row;
        if (node < N_NODES) {
            float dv = g_dinv[node];
            const float* p = &sOut[row * 64 + hsel * 32];
            uint4* dst = (uint4*)&g_h2[(size_t)node * 32 + hsel * 16];
#pragma unroll
            for (int q = 0; q < 4; q++) {
                __half2 h0 = __floats2half2_rn(p[q*8+0]*dv, p[q*8+1]*dv);
                __half2 h1 = __floats2half2_rn(p[q*8+2]*dv, p[q*8+3]*dv);
                __half2 h2 = __floats2half2_rn(p[q*8+4]*dv, p[q*8+5]*dv);
                __half2 h3 = __floats2half2_rn(p[q*8+6]*dv, p[q*8+7]*dv);
                dst[q] = make_uint4(*(uint32_t*)&h0, *(uint32_t*)&h1,
                                    *(uint32_t*)&h2, *(uint32_t*)&h3);
            }
        }
    }
}

// ------- aggregate (R12): LDG.64 half-warp edge pairing ---------------------
__device__ __forceinline__ void acc4(float& ax, float& ay, float& az, float& aw,
                                     float2 v) {
    float2 p = __half22float2(*(const __half2*)&v.x);
    float2 q = __half22float2(*(const __half2*)&v.y);
    ax += p.x; ay += p.y; az += q.x; aw += q.y;
}

__global__ void aggregate_kernel(const float* __restrict__ b, int dst) {
    int node = blockIdx.x * 8 + (threadIdx.x >> 5);
    int lane = threadIdx.x & 31;
    if (node >= N_NODES) return;
    int half = lane >> 4;
    int fl   = lane & 15;

    const float2* H = (const float2*)g_h2;   // row = 16 float2 = 128B
    int beg = g_off[node], end = g_off[node + 1];
    float ax = 0.f, ay = 0.f, az = 0.f, aw = 0.f;

    int e = beg;
    for (; e < end && (e & 3); e++) {
        if (half == 0) acc4(ax, ay, az, aw, __ldg(&H[__ldg(&g_src[e]) * 16 + fl]));
    }
    const int4* s4 = (const int4*)g_src;
    for (; e + 8 <= end; e += 8) {
        int4 i0 = __ldg(&s4[e >> 2]);
        int4 i1 = __ldg(&s4[(e >> 2) + 1]);
        int sA = half ? i0.y : i0.x;
        int sB = half ? i0.w : i0.z;
        int sC = half ? i1.y : i1.x;
        int sD = half ? i1.w : i1.z;
        float2 vA = __ldg(&H[sA * 16 + fl]);
        float2 vB = __ldg(&H[sB * 16 + fl]);
        float2 vC = __ldg(&H[sC * 16 + fl]);
        float2 vD = __ldg(&H[sD * 16 + fl]);
        acc4(ax, ay, az, aw, vA);
        acc4(ax, ay, az, aw, vB);
        acc4(ax, ay, az, aw, vC);
        acc4(ax, ay, az, aw, vD);
    }
    if (e + 4 <= end) {
        int4 i0 = __ldg(&s4[e >> 2]);
        int sA = half ? i0.y : i0.x;
        int sB = half ? i0.w : i0.z;
        float2 vA = __ldg(&H[sA * 16 + fl]);
        float2 vB = __ldg(&H[sB * 16 + fl]);
        acc4(ax, ay, az, aw, vA);
        acc4(ax, ay, az, aw, vB);
        e += 4;
    }
    for (; e < end; e++) {
        if (half == 0) acc4(ax, ay, az, aw, __ldg(&H[__ldg(&g_src[e]) * 16 + fl]));
    }

    ax += __shfl_xor_sync(0xffffffff, ax, 16);
    ay += __shfl_xor_sync(0xffffffff, ay, 16);
    az += __shfl_xor_sync(0xffffffff, az, 16);
    aw += __shfl_xor_sync(0xffffffff, aw, 16);

    if (half == 0) {
        float di = g_dinv[node];
        float4 bb = __ldg(&((const float4*)b)[fl]);
        float vx = fmaxf(fmaf(ax, di, bb.x), 0.0f);
        float vy = fmaxf(fmaf(ay, di, bb.y), 0.0f);
        float vz = fmaxf(fmaf(az, di, bb.z), 0.0f);
        float vw = fmaxf(fmaf(aw, di, bb.w), 0.0f);
        __half2 h0 = __floats2half2_rn(vx, vy);
        __half2 h1 = __floats2half2_rn(vz, vw);
        float2 st;
        *(__half2*)&st.x = h0;
        *(__half2*)&st.y = h1;
        float2* out = (float2*)((dst == 1) ? g_xh1 : (dst == 2) ? g_xh2 : g_xh3);
        out[node * 16 + fl] = st;
    }
}

// ---------------- pooling over sorted batch ----------------------------------
__global__ void start_set_kernel(const int* __restrict__ batch) {
    int i = blockIdx.x * blockDim.x + threadIdx.x;
    if (i >= N_NODES) return;
    int bcur = batch[i];
    if ((unsigned)bcur >= N_GRAPHS) return;
    if (i == 0 || batch[i - 1] != bcur) g_start[bcur] = i;
    if (i == 0) g_start[N_GRAPHS] = N_NODES;
}

__global__ void start_fix_kernel() {
    __shared__ int s[N_GRAPHS + 1];
    int t = threadIdx.x;
    for (int k = t; k <= N_GRAPHS; k += blockDim.x) s[k] = g_start[k];
    __syncthreads();
    if (t == 0) {
        int nxt = s[N_GRAPHS];
        for (int g = N_GRAPHS - 1; g >= 0; --g) {
            if (s[g] < 0) s[g] = nxt;
            nxt = s[g];
        }
    }
    __syncthreads();
    for (int k = t; k <= N_GRAPHS; k += blockDim.x) g_start[k] = s[k];
}

__global__ void pool_kernel() {
    int g = blockIdx.x;
    int t = threadIdx.x;                  // 0..95
    int layer = t >> 5, p = t & 31;
    int beg = g_start[g], end = g_start[g + 1];
    const __half2* src = (layer == 0) ? g_xh1 : (layer == 1) ? g_xh2 : g_xh3;
    float x0 = 0.f, y0 = 0.f, x1 = 0.f, y1 = 0.f;
    float x2 = 0.f, y2 = 0.f, x3 = 0.f, y3 = 0.f;
    int n = beg;
    for (; n + 4 <= end; n += 4) {
        float2 v0 = __half22float2(src[(n + 0) * 32 + p]);
        float2 v1 = __half22float2(src[(n + 1) * 32 + p]);
        float2 v2 = __half22float2(src[(n + 2) * 32 + p]);
        float2 v3 = __half22float2(src[(n + 3) * 32 + p]);
        x0 += v0.x; y0 += v0.y;  x1 += v1.x; y1 += v1.y;
        x2 += v2.x; y2 += v2.y;  x3 += v3.x; y3 += v3.y;
    }
    for (; n < end; n++) {
        float2 v = __half22float2(src[n * 32 + p]);
        x0 += v.x; y0 += v.y;
    }
    float inv = 1.0f / (float)max(end - beg, 1);
    float2* dst = (float2*)&g_pool[g * (3 * F_HID)];
    dst[layer * 32 + p] = make_float2(((x0 + x1) + (x2 + x3)) * inv,
                                      ((y0 + y1) + (y2 + y3)) * inv);
}

__global__ void final_kernel(const float* __restrict__ Wf,
                             const float* __restrict__ bf,
                             float* __restrict__ out) {
    int g = blockIdx.x;
    int j = threadIdx.x;
    float logit = __int_as_float(0xff800000);
    if (j < F_OUT) {
        float acc = bf[j];
        const float* p = g_pool + g * (3 * F_HID);
#pragma unroll 16
        for (int k = 0; k < 3 * F_HID; k++)
            acc = fmaf(p[k], Wf[k * F_OUT + j], acc);
        logit = acc;
    }
    float m = logit;
    for (int o = 16; o; o >>= 1) m = fmaxf(m, __shfl_xor_sync(0xffffffff, m, o));
    float ex = (j < F_OUT) ? expf(logit - m) : 0.0f;
    float s = ex;
    for (int o = 16; o; o >>= 1) s += __shfl_xor_sync(0xffffffff, s, o);
    if (j < F_OUT) out[g * F_OUT + j] = ex / s;
}

// ---------------- launch -----------------------------------------------------
// tgemm1 stays 4th: the fixed ncu window (-s 5 -c 1) profiles launch #4.
extern "C" void kernel_launch(void* const* d_in, const int* in_sizes, int n_in,
                              void* d_out, int out_size) {
    const float* X0    = (const float*)d_in[0];
    const int*   ei    = (const int*)d_in[1];    // int32 (JAX x64 disabled)
    const int*   batch = (const int*)d_in[2];
    const float* W1    = (const float*)d_in[3];
    const float* b1    = (const float*)d_in[4];
    const float* W2    = (const float*)d_in[5];
    const float* b2    = (const float*)d_in[6];
    const float* W3    = (const float*)d_in[7];
    const float* b3    = (const float*)d_in[8];
    const float* Wf    = (const float*)d_in[9];
    const float* bf    = (const float*)d_in[10];
    float* out = (float*)d_out;

    const int TB = 256;
    const int gridE4 = (N_EDGES / 4 + TB - 1) / TB;
    const int gridN  = (N_NODES + TB - 1) / TB;
    const int grid8  = (N_NODES + 7) / 8;

    init_kernel<<<256, TB>>>();                          // 1
    count_kernel<<<gridE4, TB>>>(ei);                    // 2
    scan1_kernel<<<NBLK, SCAN_B>>>();                    // 3 (dinv ready)
    tgemm_kernel<F_IN><<<TG_GRID, 128>>>(X0, W1, 0);     // 4 <- profiled
    scan2_kernel<<<1, 256>>>();                          // 5
    scan3_kernel<<<gridN, TB>>>();                       // 6 (primes cursor)
    scatter_kernel<<<gridE4, TB>>>(ei);                  // 7
    start_set_kernel<<<gridN, TB>>>(batch);              // 8
    start_fix_kernel<<<1, 256>>>();                      // 9

    aggregate_kernel<<<grid8, TB>>>(b1, 1);              // 10
    tgemm_kernel<F_HID><<<TG_GRID, 128>>>(nullptr, W2, 1);
    aggregate_kernel<<<grid8, TB>>>(b2, 2);
    tgemm_kernel<F_HID><<<TG_GRID, 128>>>(nullptr, W3, 2);
    aggregate_kernel<<<grid8, TB>>>(b3, 3);

    pool_kernel<<<N_GRAPHS, 96>>>();
    final_kernel<<<N_GRAPHS, 32>>>(Wf, bf, out);
}

// round 15
// speedup vs baseline: 1.1406x; 1.1406x over previous
#include <cuda_runtime.h>
#include <cuda_fp16.h>
#include <mma.h>
#include <math.h>
#include <stdint.h>

using namespace nvcuda;

#define N_NODES  100000
#define N_EDGES  3200000
#define N_GRAPHS 512
#define F_IN     128
#define F_HID    64
#define F_OUT    10

#define SCAN_B   512
#define NBLK     ((N_NODES + SCAN_B - 1) / SCAN_B)   // 196

#define TG_GRID  1184

// ---------------- scratch (device globals: no allocation allowed) ----------
__device__ int     g_count [N_NODES];
__device__ int     g_cursor[N_NODES];
__device__ int     g_off   [N_NODES + 1];
__device__ int     g_bsum  [NBLK];
__device__ int     g_boff  [NBLK];
__device__ int     g_src   [N_EDGES];
__device__ float   g_dinv  [N_NODES];
__device__ __half2 g_x0h   [N_NODES * 64];   // X0 pre-converted to fp16
__device__ __half2 g_h2    [N_NODES * 32];   // messages, fp16, pre-scaled
__device__ __half2 g_xh1   [N_NODES * 32];   // activations, fp16
__device__ __half2 g_xh2   [N_NODES * 32];
__device__ __half2 g_xh3   [N_NODES * 32];
__device__ int     g_start [N_GRAPHS + 1];
__device__ float   g_pool  [N_GRAPHS * 3 * F_HID];

// ---------------- prep -------------------------------------------------------
// init scratch + convert X0 fp32 -> fp16 (pure streaming, high MLP)
__global__ void init_kernel(const float* __restrict__ X0) {
    int i = blockIdx.x * blockDim.x + threadIdx.x;
    int stride = gridDim.x * blockDim.x;
    for (int k = i; k < N_NODES; k += stride) g_count[k] = 0;
    for (int k = i; k <= N_GRAPHS; k += stride) g_start[k] = -1;
    const float4* s = (const float4*)X0;
    uint2* d = (uint2*)g_x0h;
    for (int k = i; k < N_NODES * F_IN / 4; k += stride) {
        float4 v = __ldg(&s[k]);
        __half2 a = __floats2half2_rn(v.x, v.y);
        __half2 b = __floats2half2_rn(v.z, v.w);
        d[k] = make_uint2(*(uint32_t*)&a, *(uint32_t*)&b);
    }
}

__global__ void count_kernel(const int* __restrict__ ei) {
    int t = blockIdx.x * blockDim.x + threadIdx.x;
    if (t >= N_EDGES / 4) return;
    int4 c = __ldg(&((const int4*)(ei + N_EDGES))[t]);
    if ((unsigned)c.x < N_NODES) atomicAdd(&g_count[c.x], 1);
    if ((unsigned)c.y < N_NODES) atomicAdd(&g_count[c.y], 1);
    if ((unsigned)c.z < N_NODES) atomicAdd(&g_count[c.z], 1);
    if ((unsigned)c.w < N_NODES) atomicAdd(&g_count[c.w], 1);
}

__global__ void scan1_kernel() {
    __shared__ int s[SCAN_B];
    int t = threadIdx.x;
    int i = blockIdx.x * SCAN_B + t;
    int v = (i < N_NODES) ? g_count[i] : 0;
    if (i < N_NODES) g_dinv[i] = (v > 0) ? rsqrtf((float)v) : 0.0f;
    s[t] = v; __syncthreads();
    int x = v;
    for (int o = 1; o < SCAN_B; o <<= 1) {
        int y = (t >= o) ? s[t - o] : 0;
        __syncthreads();
        x += y; s[t] = x;
        __syncthreads();
    }
    if (i < N_NODES) g_off[i] = x - v;
    if (t == SCAN_B - 1) g_bsum[blockIdx.x] = x;
}

__global__ void scan2_kernel() {
    __shared__ int s[256];
    int t = threadIdx.x;
    int v = (t < NBLK) ? g_bsum[t] : 0;
    s[t] = v; __syncthreads();
    int x = v;
    for (int o = 1; o < 256; o <<= 1) {
        int y = (t >= o) ? s[t - o] : 0;
        __syncthreads();
        x += y; s[t] = x;
        __syncthreads();
    }
    if (t < NBLK) g_boff[t] = x - v;
}

__global__ void scan3_kernel() {
    int i = blockIdx.x * blockDim.x + threadIdx.x;
    if (i < N_NODES) {
        int off = g_off[i] + g_boff[i / SCAN_B];
        g_off[i] = off;
        g_cursor[i] = off;                 // prime scatter cursors
    }
    if (i == 0) g_off[N_NODES] = N_EDGES;
}

__global__ void scatter_kernel(const int* __restrict__ ei) {
    int t = blockIdx.x * blockDim.x + threadIdx.x;
    if (t >= N_EDGES / 4) return;
    int4 r = __ldg(&((const int4*)ei)[t]);
    int4 c = __ldg(&((const int4*)(ei + N_EDGES))[t]);
    if ((unsigned)c.x < N_NODES) g_src[atomicAdd(&g_cursor[c.x], 1)] = r.x;
    if ((unsigned)c.y < N_NODES) g_src[atomicAdd(&g_cursor[c.y], 1)] = r.y;
    if ((unsigned)c.z < N_NODES) g_src[atomicAdd(&g_cursor[c.z], 1)] = r.z;
    if ((unsigned)c.w < N_NODES) g_src[atomicAdd(&g_cursor[c.w], 1)] = r.w;
}

// ------- GEMM via wmma, conflict-free smem + batched staging ----------------
// h2[n] = half2( (X[n,:K] @ W) * dinv[n] ).  128 thr = 4 warps, 64-node tile.
// All inputs fp16 (g_x0h / g_xh1 / g_xh2).  A ldm = K+8, B ldm = 72 (padded).
// C (f32, ldm 64) reuses the A staging buffer after MMA consumed it.
template <int K>
__global__ __launch_bounds__(128) void tgemm_kernel(
        const float* __restrict__ W, int src) {
    constexpr int KP   = K + 8;                 // padded A stride (halfs)
    constexpr int U4PT = (64 * K / 8) / 128;    // uint4 per thread (8 or 4)
    constexpr int XB   = 64 * KP * 2;           // A tile bytes
    constexpr int BUF  = (XB > 16384) ? XB : 16384;  // also 64x64 f32 C
    __shared__ __half        sW[K * 72];
    __shared__ unsigned char sbuf[BUF];
    __half* sXh  = (__half*)sbuf;
    float*  sOut = (float*)sbuf;

    int tid = threadIdx.x, warp = tid >> 5;

    // stage W (K x 64) -> padded (K x 72), coalesced reads
    for (int i = tid; i < K * 64; i += 128) {
        int k = i >> 6, n = i & 63;
        sW[k * 72 + n] = __float2half_rn(__ldg(&W[i]));
    }

    const uint4* Xin = (const uint4*)((src == 0) ? g_x0h
                                    : (src == 1) ? g_xh1 : g_xh2);
    const int ROW_U4 = K / 8;                   // uint4 per row
    const int TOT_U4 = N_NODES * ROW_U4;
    const int NT = (N_NODES + 63) / 64;         // 1563
    for (int tile = blockIdx.x; tile < NT; tile += gridDim.x) {
        int node0 = tile * 64;
        __syncthreads();                         // sW ready / sbuf reusable

        // batched staging: front-load all LDG.128, then store padded
        uint4 r[U4PT];
        int base = node0 * ROW_U4;
#pragma unroll
        for (int j = 0; j < U4PT; j++) {
            int gi = base + tid + j * 128;
            r[j] = (gi < TOT_U4) ? __ldg(&Xin[gi]) : make_uint4(0, 0, 0, 0);
        }
#pragma unroll
        for (int j = 0; j < U4PT; j++) {
            int i = tid + j * 128;
            int row = i / ROW_U4, c16 = i % ROW_U4;
            *(uint4*)&sXh[row * KP + c16 * 8] = r[j];
        }
        __syncthreads();

        wmma::fragment<wmma::accumulator, 16, 16, 16, float> acc[4];
#pragma unroll
        for (int j = 0; j < 4; j++) wmma::fill_fragment(acc[j], 0.0f);
        wmma::fragment<wmma::matrix_a, 16, 16, 16, __half, wmma::row_major> a;
        wmma::fragment<wmma::matrix_b, 16, 16, 16, __half, wmma::row_major> b;
        int rowBase = warp * 16;
#pragma unroll
        for (int ks = 0; ks < K / 16; ks++) {
            wmma::load_matrix_sync(a, &sXh[rowBase * KP + ks * 16], KP);
#pragma unroll
            for (int j = 0; j < 4; j++) {
                wmma::load_matrix_sync(b, &sW[ks * 16 * 72 + j * 16], 72);
                wmma::mma_sync(acc[j], a, b, acc[j]);
            }
        }
        __syncthreads();                         // all A reads done
#pragma unroll
        for (int j = 0; j < 4; j++)
            wmma::store_matrix_sync(&sOut[rowBase * 64 + j * 16], acc[j], 64,
                                    wmma::mem_row_major);
        __syncthreads();

        // fused dinv scale + fp16 pack; 2 threads per row
        int row = tid >> 1, hsel = tid & 1;
        int node = node0 + row;
        if (node < N_NODES) {
            float dv = g_dinv[node];
            const float* p = &sOut[row * 64 + hsel * 32];
            uint4* dst = (uint4*)&g_h2[(size_t)node * 32 + hsel * 16];
#pragma unroll
            for (int q = 0; q < 4; q++) {
                __half2 h0 = __floats2half2_rn(p[q*8+0]*dv, p[q*8+1]*dv);
                __half2 h1 = __floats2half2_rn(p[q*8+2]*dv, p[q*8+3]*dv);
                __half2 h2 = __floats2half2_rn(p[q*8+4]*dv, p[q*8+5]*dv);
                __half2 h3 = __floats2half2_rn(p[q*8+6]*dv, p[q*8+7]*dv);
                dst[q] = make_uint4(*(uint32_t*)&h0, *(uint32_t*)&h1,
                                    *(uint32_t*)&h2, *(uint32_t*)&h3);
            }
        }
    }
}

// ------- aggregate (R12): LDG.64 half-warp edge pairing ---------------------
__device__ __forceinline__ void acc4(float& ax, float& ay, float& az, float& aw,
                                     float2 v) {
    float2 p = __half22float2(*(const __half2*)&v.x);
    float2 q = __half22float2(*(const __half2*)&v.y);
    ax += p.x; ay += p.y; az += q.x; aw += q.y;
}

__global__ void aggregate_kernel(const float* __restrict__ b, int dst) {
    int node = blockIdx.x * 8 + (threadIdx.x >> 5);
    int lane = threadIdx.x & 31;
    if (node >= N_NODES) return;
    int half = lane >> 4;
    int fl   = lane & 15;

    const float2* H = (const float2*)g_h2;   // row = 16 float2 = 128B
    int beg = g_off[node], end = g_off[node + 1];
    float ax = 0.f, ay = 0.f, az = 0.f, aw = 0.f;

    int e = beg;
    for (; e < end && (e & 3); e++) {
        if (half == 0) acc4(ax, ay, az, aw, __ldg(&H[__ldg(&g_src[e]) * 16 + fl]));
    }
    const int4* s4 = (const int4*)g_src;
    for (; e + 8 <= end; e += 8) {
        int4 i0 = __ldg(&s4[e >> 2]);
        int4 i1 = __ldg(&s4[(e >> 2) + 1]);
        int sA = half ? i0.y : i0.x;
        int sB = half ? i0.w : i0.z;
        int sC = half ? i1.y : i1.x;
        int sD = half ? i1.w : i1.z;
        float2 vA = __ldg(&H[sA * 16 + fl]);
        float2 vB = __ldg(&H[sB * 16 + fl]);
        float2 vC = __ldg(&H[sC * 16 + fl]);
        float2 vD = __ldg(&H[sD * 16 + fl]);
        acc4(ax, ay, az, aw, vA);
        acc4(ax, ay, az, aw, vB);
        acc4(ax, ay, az, aw, vC);
        acc4(ax, ay, az, aw, vD);
    }
    if (e + 4 <= end) {
        int4 i0 = __ldg(&s4[e >> 2]);
        int sA = half ? i0.y : i0.x;
        int sB = half ? i0.w : i0.z;
        float2 vA = __ldg(&H[sA * 16 + fl]);
        float2 vB = __ldg(&H[sB * 16 + fl]);
        acc4(ax, ay, az, aw, vA);
        acc4(ax, ay, az, aw, vB);
        e += 4;
    }
    for (; e < end; e++) {
        if (half == 0) acc4(ax, ay, az, aw, __ldg(&H[__ldg(&g_src[e]) * 16 + fl]));
    }

    ax += __shfl_xor_sync(0xffffffff, ax, 16);
    ay += __shfl_xor_sync(0xffffffff, ay, 16);
    az += __shfl_xor_sync(0xffffffff, az, 16);
    aw += __shfl_xor_sync(0xffffffff, aw, 16);

    if (half == 0) {
        float di = g_dinv[node];
        float4 bb = __ldg(&((const float4*)b)[fl]);
        float vx = fmaxf(fmaf(ax, di, bb.x), 0.0f);
        float vy = fmaxf(fmaf(ay, di, bb.y), 0.0f);
        float vz = fmaxf(fmaf(az, di, bb.z), 0.0f);
        float vw = fmaxf(fmaf(aw, di, bb.w), 0.0f);
        __half2 h0 = __floats2half2_rn(vx, vy);
        __half2 h1 = __floats2half2_rn(vz, vw);
        float2 st;
        *(__half2*)&st.x = h0;
        *(__half2*)&st.y = h1;
        float2* out = (float2*)((dst == 1) ? g_xh1 : (dst == 2) ? g_xh2 : g_xh3);
        out[node * 16 + fl] = st;
    }
}

// ---------------- pooling over sorted batch ----------------------------------
__global__ void start_set_kernel(const int* __restrict__ batch) {
    int i = blockIdx.x * blockDim.x + threadIdx.x;
    if (i >= N_NODES) return;
    int bcur = batch[i];
    if ((unsigned)bcur >= N_GRAPHS) return;
    if (i == 0 || batch[i - 1] != bcur) g_start[bcur] = i;
    if (i == 0) g_start[N_GRAPHS] = N_NODES;
}

__global__ void start_fix_kernel() {
    __shared__ int s[N_GRAPHS + 1];
    int t = threadIdx.x;
    for (int k = t; k <= N_GRAPHS; k += blockDim.x) s[k] = g_start[k];
    __syncthreads();
    if (t == 0) {
        int nxt = s[N_GRAPHS];
        for (int g = N_GRAPHS - 1; g >= 0; --g) {
            if (s[g] < 0) s[g] = nxt;
            nxt = s[g];
        }
    }
    __syncthreads();
    for (int k = t; k <= N_GRAPHS; k += blockDim.x) g_start[k] = s[k];
}

__global__ void pool_kernel() {
    int g = blockIdx.x;
    int t = threadIdx.x;                  // 0..95
    int layer = t >> 5, p = t & 31;
    int beg = g_start[g], end = g_start[g + 1];
    const __half2* src = (layer == 0) ? g_xh1 : (layer == 1) ? g_xh2 : g_xh3;
    float x0 = 0.f, y0 = 0.f, x1 = 0.f, y1 = 0.f;
    float x2 = 0.f, y2 = 0.f, x3 = 0.f, y3 = 0.f;
    int n = beg;
    for (; n + 4 <= end; n += 4) {
        float2 v0 = __half22float2(src[(n + 0) * 32 + p]);
        float2 v1 = __half22float2(src[(n + 1) * 32 + p]);
        float2 v2 = __half22float2(src[(n + 2) * 32 + p]);
        float2 v3 = __half22float2(src[(n + 3) * 32 + p]);
        x0 += v0.x; y0 += v0.y;  x1 += v1.x; y1 += v1.y;
        x2 += v2.x; y2 += v2.y;  x3 += v3.x; y3 += v3.y;
    }
    for (; n < end; n++) {
        float2 v = __half22float2(src[n * 32 + p]);
        x0 += v.x; y0 += v.y;
    }
    float inv = 1.0f / (float)max(end - beg, 1);
    float2* dst = (float2*)&g_pool[g * (3 * F_HID)];
    dst[layer * 32 + p] = make_float2(((x0 + x1) + (x2 + x3)) * inv,
                                      ((y0 + y1) + (y2 + y3)) * inv);
}

__global__ void final_kernel(const float* __restrict__ Wf,
                             const float* __restrict__ bf,
                             float* __restrict__ out) {
    int g = blockIdx.x;
    int j = threadIdx.x;
    float logit = __int_as_float(0xff800000);
    if (j < F_OUT) {
        float acc = bf[j];
        const float* p = g_pool + g * (3 * F_HID);
#pragma unroll 16
        for (int k = 0; k < 3 * F_HID; k++)
            acc = fmaf(p[k], Wf[k * F_OUT + j], acc);
        logit = acc;
    }
    float m = logit;
    for (int o = 16; o; o >>= 1) m = fmaxf(m, __shfl_xor_sync(0xffffffff, m, o));
    float ex = (j < F_OUT) ? expf(logit - m) : 0.0f;
    float s = ex;
    for (int o = 16; o; o >>= 1) s += __shfl_xor_sync(0xffffffff, s, o);
    if (j < F_OUT) out[g * F_OUT + j] = ex / s;
}

// ---------------- launch -----------------------------------------------------
// gemm1 stays 4th: the fixed ncu window profiles launch #4.
extern "C" void kernel_launch(void* const* d_in, const int* in_sizes, int n_in,
                              void* d_out, int out_size) {
    const float* X0    = (const float*)d_in[0];
    const int*   ei    = (const int*)d_in[1];    // int32 (JAX x64 disabled)
    const int*   batch = (const int*)d_in[2];
    const float* W1    = (const float*)d_in[3];
    const float* b1    = (const float*)d_in[4];
    const float* W2    = (const float*)d_in[5];
    const float* b2    = (const float*)d_in[6];
    const float* W3    = (const float*)d_in[7];
    const float* b3    = (const float*)d_in[8];
    const float* Wf    = (const float*)d_in[9];
    const float* bf    = (const float*)d_in[10];
    float* out = (float*)d_out;

    const int TB = 256;
    const int gridE4 = (N_EDGES / 4 + TB - 1) / TB;
    const int gridN  = (N_NODES + TB - 1) / TB;
    const int grid8  = (N_NODES + 7) / 8;

    init_kernel<<<2048, TB>>>(X0);                       // 1 (+X0 fp16 convert)
    count_kernel<<<gridE4, TB>>>(ei);                    // 2
    scan1_kernel<<<NBLK, SCAN_B>>>();                    // 3 (dinv ready)
    tgemm_kernel<F_IN><<<TG_GRID, 128>>>(W1, 0);         // 4 <- profiled
    scan2_kernel<<<1, 256>>>();                          // 5
    scan3_kernel<<<gridN, TB>>>();                       // 6 (primes cursor)
    scatter_kernel<<<gridE4, TB>>>(ei);                  // 7
    start_set_kernel<<<gridN, TB>>>(batch);              // 8
    start_fix_kernel<<<1, 256>>>();                      // 9

    aggregate_kernel<<<grid8, TB>>>(b1, 1);              // 10
    tgemm_kernel<F_HID><<<TG_GRID, 128>>>(W2, 1);
    aggregate_kernel<<<grid8, TB>>>(b2, 2);
    tgemm_kernel<F_HID><<<TG_GRID, 128>>>(W3, 2);
    aggregate_kernel<<<grid8, TB>>>(b3, 3);

    pool_kernel<<<N_GRAPHS, 96>>>();
    final_kernel<<<N_GRAPHS, 32>>>(Wf, bf, out);
}

// round 16
// speedup vs baseline: 1.1700x; 1.0258x over previous
#include <cuda_runtime.h>
#include <cuda_fp16.h>
#include <cuda_fp8.h>
#include <mma.h>
#include <math.h>
#include <stdint.h>

using namespace nvcuda;

#define N_NODES  100000
#define N_EDGES  3200000
#define N_GRAPHS 512
#define F_IN     128
#define F_HID    64
#define F_OUT    10

#define SCAN_B   512
#define NBLK     ((N_NODES + SCAN_B - 1) / SCAN_B)   // 196

#define TG_GRID  1184

// ---------------- scratch (device globals: no allocation allowed) ----------
__device__ int      g_count [N_NODES];
__device__ int      g_cursor[N_NODES];
__device__ int      g_off   [N_NODES + 1];
__device__ int      g_bsum  [NBLK];
__device__ int      g_boff  [NBLK];
__device__ int      g_src   [N_EDGES];
__device__ float    g_dinv  [N_NODES];
__device__ __half2  g_x0h   [N_NODES * 64];   // X0 pre-converted to fp16
__device__ uint32_t g_q8    [N_NODES * 16];   // messages, e4m3 fp8 (64B/row)
__device__ __half2  g_xh1   [N_NODES * 32];   // activations, fp16
__device__ __half2  g_xh2   [N_NODES * 32];
__device__ __half2  g_xh3   [N_NODES * 32];
__device__ int      g_start [N_GRAPHS + 1];
__device__ float    g_pool  [N_GRAPHS * 3 * F_HID];

// ---------------- fp8 helpers ------------------------------------------------
__device__ __forceinline__ uint32_t pack_fp8x4(float a, float b, float c,
                                               float d) {
    __nv_fp8x2_storage_t lo =
        __nv_cvt_float2_to_fp8x2(make_float2(a, b), __NV_SATFINITE, __NV_E4M3);
    __nv_fp8x2_storage_t hi =
        __nv_cvt_float2_to_fp8x2(make_float2(c, d), __NV_SATFINITE, __NV_E4M3);
    return (uint32_t)lo | ((uint32_t)hi << 16);
}
__device__ __forceinline__ void dq4(float& ax, float& ay, float& az, float& aw,
                                    uint32_t v) {
    __half2_raw h0 = __nv_cvt_fp8x2_to_halfraw2(
        (__nv_fp8x2_storage_t)(v & 0xFFFF), __NV_E4M3);
    __half2_raw h1 = __nv_cvt_fp8x2_to_halfraw2(
        (__nv_fp8x2_storage_t)(v >> 16), __NV_E4M3);
    float2 p = __half22float2(*(__half2*)&h0);
    float2 q = __half22float2(*(__half2*)&h1);
    ax += p.x; ay += p.y; az += q.x; aw += q.y;
}

// ---------------- prep -------------------------------------------------------
__global__ void init_kernel(const float* __restrict__ X0) {
    int i = blockIdx.x * blockDim.x + threadIdx.x;
    int stride = gridDim.x * blockDim.x;
    for (int k = i; k < N_NODES; k += stride) g_count[k] = 0;
    for (int k = i; k <= N_GRAPHS; k += stride) g_start[k] = -1;
    const float4* s = (const float4*)X0;
    uint2* d = (uint2*)g_x0h;
    for (int k = i; k < N_NODES * F_IN / 4; k += stride) {
        float4 v = __ldg(&s[k]);
        __half2 a = __floats2half2_rn(v.x, v.y);
        __half2 b = __floats2half2_rn(v.z, v.w);
        d[k] = make_uint2(*(uint32_t*)&a, *(uint32_t*)&b);
    }
}

__global__ void count_kernel(const int* __restrict__ ei) {
    int t = blockIdx.x * blockDim.x + threadIdx.x;
    if (t >= N_EDGES / 4) return;
    int4 c = __ldg(&((const int4*)(ei + N_EDGES))[t]);
    if ((unsigned)c.x < N_NODES) atomicAdd(&g_count[c.x], 1);
    if ((unsigned)c.y < N_NODES) atomicAdd(&g_count[c.y], 1);
    if ((unsigned)c.z < N_NODES) atomicAdd(&g_count[c.z], 1);
    if ((unsigned)c.w < N_NODES) atomicAdd(&g_count[c.w], 1);
}

__global__ void scan1_kernel() {
    __shared__ int s[SCAN_B];
    int t = threadIdx.x;
    int i = blockIdx.x * SCAN_B + t;
    int v = (i < N_NODES) ? g_count[i] : 0;
    if (i < N_NODES) g_dinv[i] = (v > 0) ? rsqrtf((float)v) : 0.0f;
    s[t] = v; __syncthreads();
    int x = v;
    for (int o = 1; o < SCAN_B; o <<= 1) {
        int y = (t >= o) ? s[t - o] : 0;
        __syncthreads();
        x += y; s[t] = x;
        __syncthreads();
    }
    if (i < N_NODES) g_off[i] = x - v;
    if (t == SCAN_B - 1) g_bsum[blockIdx.x] = x;
}

__global__ void scan2_kernel() {
    __shared__ int s[256];
    int t = threadIdx.x;
    int v = (t < NBLK) ? g_bsum[t] : 0;
    s[t] = v; __syncthreads();
    int x = v;
    for (int o = 1; o < 256; o <<= 1) {
        int y = (t >= o) ? s[t - o] : 0;
        __syncthreads();
        x += y; s[t] = x;
        __syncthreads();
    }
    if (t < NBLK) g_boff[t] = x - v;
}

__global__ void scan3_kernel() {
    int i = blockIdx.x * blockDim.x + threadIdx.x;
    if (i < N_NODES) {
        int off = g_off[i] + g_boff[i / SCAN_B];
        g_off[i] = off;
        g_cursor[i] = off;                 // prime scatter cursors
    }
    if (i == 0) g_off[N_NODES] = N_EDGES;
}

__global__ void scatter_kernel(const int* __restrict__ ei) {
    int t = blockIdx.x * blockDim.x + threadIdx.x;
    if (t >= N_EDGES / 4) return;
    int4 r = __ldg(&((const int4*)ei)[t]);
    int4 c = __ldg(&((const int4*)(ei + N_EDGES))[t]);
    if ((unsigned)c.x < N_NODES) g_src[atomicAdd(&g_cursor[c.x], 1)] = r.x;
    if ((unsigned)c.y < N_NODES) g_src[atomicAdd(&g_cursor[c.y], 1)] = r.y;
    if ((unsigned)c.z < N_NODES) g_src[atomicAdd(&g_cursor[c.z], 1)] = r.z;
    if ((unsigned)c.w < N_NODES) g_src[atomicAdd(&g_cursor[c.w], 1)] = r.w;
}

// ------- GEMM via wmma (R15) with fp8 message output ------------------------
// q8[n] = e4m3( (X[n,:K] @ W) * dinv[n] ).  128 thr = 4 warps, 64-node tile.
template <int K>
__global__ __launch_bounds__(128) void tgemm_kernel(
        const float* __restrict__ W, int src) {
    constexpr int KP   = K + 8;
    constexpr int U4PT = (64 * K / 8) / 128;
    constexpr int XB   = 64 * KP * 2;
    constexpr int BUF  = (XB > 16384) ? XB : 16384;
    __shared__ __half        sW[K * 72];
    __shared__ unsigned char sbuf[BUF];
    __half* sXh  = (__half*)sbuf;
    float*  sOut = (float*)sbuf;

    int tid = threadIdx.x, warp = tid >> 5;

    for (int i = tid; i < K * 64; i += 128) {
        int k = i >> 6, n = i & 63;
        sW[k * 72 + n] = __float2half_rn(__ldg(&W[i]));
    }

    const uint4* Xin = (const uint4*)((src == 0) ? g_x0h
                                    : (src == 1) ? g_xh1 : g_xh2);
    const int ROW_U4 = K / 8;
    const int TOT_U4 = N_NODES * ROW_U4;
    const int NT = (N_NODES + 63) / 64;
    for (int tile = blockIdx.x; tile < NT; tile += gridDim.x) {
        int node0 = tile * 64;
        __syncthreads();

        uint4 r[U4PT];
        int base = node0 * ROW_U4;
#pragma unroll
        for (int j = 0; j < U4PT; j++) {
            int gi = base + tid + j * 128;
            r[j] = (gi < TOT_U4) ? __ldg(&Xin[gi]) : make_uint4(0, 0, 0, 0);
        }
#pragma unroll
        for (int j = 0; j < U4PT; j++) {
            int i = tid + j * 128;
            int row = i / ROW_U4, c16 = i % ROW_U4;
            *(uint4*)&sXh[row * KP + c16 * 8] = r[j];
        }
        __syncthreads();

        wmma::fragment<wmma::accumulator, 16, 16, 16, float> acc[4];
#pragma unroll
        for (int j = 0; j < 4; j++) wmma::fill_fragment(acc[j], 0.0f);
        wmma::fragment<wmma::matrix_a, 16, 16, 16, __half, wmma::row_major> a;
        wmma::fragment<wmma::matrix_b, 16, 16, 16, __half, wmma::row_major> b;
        int rowBase = warp * 16;
#pragma unroll
        for (int ks = 0; ks < K / 16; ks++) {
            wmma::load_matrix_sync(a, &sXh[rowBase * KP + ks * 16], KP);
#pragma unroll
            for (int j = 0; j < 4; j++) {
                wmma::load_matrix_sync(b, &sW[ks * 16 * 72 + j * 16], 72);
                wmma::mma_sync(acc[j], a, b, acc[j]);
            }
        }
        __syncthreads();
#pragma unroll
        for (int j = 0; j < 4; j++)
            wmma::store_matrix_sync(&sOut[rowBase * 64 + j * 16], acc[j], 64,
                                    wmma::mem_row_major);
        __syncthreads();

        // fused dinv scale + e4m3 pack; 2 threads per row (32 vals each)
        int row = tid >> 1, hsel = tid & 1;
        int node = node0 + row;
        if (node < N_NODES) {
            float dv = g_dinv[node];
            const float* p = &sOut[row * 64 + hsel * 32];
            uint4* dst = (uint4*)&g_q8[(size_t)node * 16 + hsel * 8];
#pragma unroll
            for (int q = 0; q < 2; q++) {
                uint4 o;
                o.x = pack_fp8x4(p[q*16+ 0]*dv, p[q*16+ 1]*dv,
                                 p[q*16+ 2]*dv, p[q*16+ 3]*dv);
                o.y = pack_fp8x4(p[q*16+ 4]*dv, p[q*16+ 5]*dv,
                                 p[q*16+ 6]*dv, p[q*16+ 7]*dv);
                o.z = pack_fp8x4(p[q*16+ 8]*dv, p[q*16+ 9]*dv,
                                 p[q*16+10]*dv, p[q*16+11]*dv);
                o.w = pack_fp8x4(p[q*16+12]*dv, p[q*16+13]*dv,
                                 p[q*16+14]*dv, p[q*16+15]*dv);
                dst[q] = o;
            }
        }
    }
}

// ------- aggregate: fp8 gather (64B rows), half-warp edge pairing -----------
// lane = (half, fl): fl covers features 4fl..4fl+3 via one uint32 (4 fp8).
__global__ void aggregate_kernel(const float* __restrict__ b, int dst) {
    int node = blockIdx.x * 8 + (threadIdx.x >> 5);
    int lane = threadIdx.x & 31;
    if (node >= N_NODES) return;
    int half = lane >> 4;
    int fl   = lane & 15;

    const uint32_t* Q = g_q8;                // row = 16 uint32 = 64B
    int beg = g_off[node], end = g_off[node + 1];
    float ax = 0.f, ay = 0.f, az = 0.f, aw = 0.f;

    int e = beg;
    for (; e < end && (e & 3); e++) {
        if (half == 0) dq4(ax, ay, az, aw, __ldg(&Q[__ldg(&g_src[e]) * 16 + fl]));
    }
    const int4* s4 = (const int4*)g_src;
    for (; e + 8 <= end; e += 8) {
        int4 i0 = __ldg(&s4[e >> 2]);
        int4 i1 = __ldg(&s4[(e >> 2) + 1]);
        int sA = half ? i0.y : i0.x;
        int sB = half ? i0.w : i0.z;
        int sC = half ? i1.y : i1.x;
        int sD = half ? i1.w : i1.z;
        uint32_t vA = __ldg(&Q[sA * 16 + fl]);
        uint32_t vB = __ldg(&Q[sB * 16 + fl]);
        uint32_t vC = __ldg(&Q[sC * 16 + fl]);
        uint32_t vD = __ldg(&Q[sD * 16 + fl]);
        dq4(ax, ay, az, aw, vA);
        dq4(ax, ay, az, aw, vB);
        dq4(ax, ay, az, aw, vC);
        dq4(ax, ay, az, aw, vD);
    }
    if (e + 4 <= end) {
        int4 i0 = __ldg(&s4[e >> 2]);
        int sA = half ? i0.y : i0.x;
        int sB = half ? i0.w : i0.z;
        uint32_t vA = __ldg(&Q[sA * 16 + fl]);
        uint32_t vB = __ldg(&Q[sB * 16 + fl]);
        dq4(ax, ay, az, aw, vA);
        dq4(ax, ay, az, aw, vB);
        e += 4;
    }
    for (; e < end; e++) {
        if (half == 0) dq4(ax, ay, az, aw, __ldg(&Q[__ldg(&g_src[e]) * 16 + fl]));
    }

    ax += __shfl_xor_sync(0xffffffff, ax, 16);
    ay += __shfl_xor_sync(0xffffffff, ay, 16);
    az += __shfl_xor_sync(0xffffffff, az, 16);
    aw += __shfl_xor_sync(0xffffffff, aw, 16);

    if (half == 0) {
        float di = g_dinv[node];
        float4 bb = __ldg(&((const float4*)b)[fl]);
        float vx = fmaxf(fmaf(ax, di, bb.x), 0.0f);
        float vy = fmaxf(fmaf(ay, di, bb.y), 0.0f);
        float vz = fmaxf(fmaf(az, di, bb.z), 0.0f);
        float vw = fmaxf(fmaf(aw, di, bb.w), 0.0f);
        __half2 h0 = __floats2half2_rn(vx, vy);
        __half2 h1 = __floats2half2_rn(vz, vw);
        float2 st;
        *(__half2*)&st.x = h0;
        *(__half2*)&st.y = h1;
        float2* out = (float2*)((dst == 1) ? g_xh1 : (dst == 2) ? g_xh2 : g_xh3);
        out[node * 16 + fl] = st;
    }
}

// ---------------- pooling over sorted batch ----------------------------------
__global__ void start_set_kernel(const int* __restrict__ batch) {
    int i = blockIdx.x * blockDim.x + threadIdx.x;
    if (i >= N_NODES) return;
    int bcur = batch[i];
    if ((unsigned)bcur >= N_GRAPHS) return;
    if (i == 0 || batch[i - 1] != bcur) g_start[bcur] = i;
    if (i == 0) g_start[N_GRAPHS] = N_NODES;
}

__global__ void start_fix_kernel() {
    __shared__ int s[N_GRAPHS + 1];
    int t = threadIdx.x;
    for (int k = t; k <= N_GRAPHS; k += blockDim.x) s[k] = g_start[k];
    __syncthreads();
    if (t == 0) {
        int nxt = s[N_GRAPHS];
        for (int g = N_GRAPHS - 1; g >= 0; --g) {
            if (s[g] < 0) s[g] = nxt;
            nxt = s[g];
        }
    }
    __syncthreads();
    for (int k = t; k <= N_GRAPHS; k += blockDim.x) g_start[k] = s[k];
}

__global__ void pool_kernel() {
    int g = blockIdx.x;
    int t = threadIdx.x;                  // 0..95
    int layer = t >> 5, p = t & 31;
    int beg = g_start[g], end = g_start[g + 1];
    const __half2* src = (layer == 0) ? g_xh1 : (layer == 1) ? g_xh2 : g_xh3;
    float x0 = 0.f, y0 = 0.f, x1 = 0.f, y1 = 0.f;
    float x2 = 0.f, y2 = 0.f, x3 = 0.f, y3 = 0.f;
    int n = beg;
    for (; n + 4 <= end; n += 4) {
        float2 v0 = __half22float2(src[(n + 0) * 32 + p]);
        float2 v1 = __half22float2(src[(n + 1) * 32 + p]);
        float2 v2 = __half22float2(src[(n + 2) * 32 + p]);
        float2 v3 = __half22float2(src[(n + 3) * 32 + p]);
        x0 += v0.x; y0 += v0.y;  x1 += v1.x; y1 += v1.y;
        x2 += v2.x; y2 += v2.y;  x3 += v3.x; y3 += v3.y;
    }
    for (; n < end; n++) {
        float2 v = __half22float2(src[n * 32 + p]);
        x0 += v.x; y0 += v.y;
    }
    float inv = 1.0f / (float)max(end - beg, 1);
    float2* dst = (float2*)&g_pool[g * (3 * F_HID)];
    dst[layer * 32 + p] = make_float2(((x0 + x1) + (x2 + x3)) * inv,
                                      ((y0 + y1) + (y2 + y3)) * inv);
}

__global__ void final_kernel(const float* __restrict__ Wf,
                             const float* __restrict__ bf,
                             float* __restrict__ out) {
    int g = blockIdx.x;
    int j = threadIdx.x;
    float logit = __int_as_float(0xff800000);
    if (j < F_OUT) {
        float acc = bf[j];
        const float* p = g_pool + g * (3 * F_HID);
#pragma unroll 16
        for (int k = 0; k < 3 * F_HID; k++)
            acc = fmaf(p[k], Wf[k * F_OUT + j], acc);
        logit = acc;
    }
    float m = logit;
    for (int o = 16; o; o >>= 1) m = fmaxf(m, __shfl_xor_sync(0xffffffff, m, o));
    float ex = (j < F_OUT) ? expf(logit - m) : 0.0f;
    float s = ex;
    for (int o = 16; o; o >>= 1) s += __shfl_xor_sync(0xffffffff, s, o);
    if (j < F_OUT) out[g * F_OUT + j] = ex / s;
}

// ---------------- launch -----------------------------------------------------
// gemm1 stays 4th: the fixed ncu window profiles launch #4.
extern "C" void kernel_launch(void* const* d_in, const int* in_sizes, int n_in,
                              void* d_out, int out_size) {
    const float* X0    = (const float*)d_in[0];
    const int*   ei    = (const int*)d_in[1];    // int32 (JAX x64 disabled)
    const int*   batch = (const int*)d_in[2];
    const float* W1    = (const float*)d_in[3];
    const float* b1    = (const float*)d_in[4];
    const float* W2    = (const float*)d_in[5];
    const float* b2    = (const float*)d_in[6];
    const float* W3    = (const float*)d_in[7];
    const float* b3    = (const float*)d_in[8];
    const float* Wf    = (const float*)d_in[9];
    const float* bf    = (const float*)d_in[10];
    float* out = (float*)d_out;

    const int TB = 256;
    const int gridE4 = (N_EDGES / 4 + TB - 1) / TB;
    const int gridN  = (N_NODES + TB - 1) / TB;
    const int grid8  = (N_NODES + 7) / 8;

    init_kernel<<<2048, TB>>>(X0);                       // 1 (+X0 fp16 convert)
    count_kernel<<<gridE4, TB>>>(ei);                    // 2
    scan1_kernel<<<NBLK, SCAN_B>>>();                    // 3 (dinv ready)
    tgemm_kernel<F_IN><<<TG_GRID, 128>>>(W1, 0);         // 4 <- profiled
    scan2_kernel<<<1, 256>>>();                          // 5
    scan3_kernel<<<gridN, TB>>>();                       // 6 (primes cursor)
    scatter_kernel<<<gridE4, TB>>>(ei);                  // 7
    start_set_kernel<<<gridN, TB>>>(batch);              // 8
    start_fix_kernel<<<1, 256>>>();                      // 9

    aggregate_kernel<<<grid8, TB>>>(b1, 1);              // 10
    tgemm_kernel<F_HID><<<TG_GRID, 128>>>(W2, 1);
    aggregate_kernel<<<grid8, TB>>>(b2, 2);
    tgemm_kernel<F_HID><<<TG_GRID, 128>>>(W3, 2);
    aggregate_kernel<<<grid8, TB>>>(b3, 3);

    pool_kernel<<<N_GRAPHS, 96>>>();
    final_kernel<<<N_GRAPHS, 32>>>(Wf, bf, out);
}

// round 17
// speedup vs baseline: 1.2548x; 1.0725x over previous
#include <cuda_runtime.h>
#include <cuda_fp16.h>
#include <cuda_fp8.h>
#include <mma.h>
#include <math.h>
#include <stdint.h>

using namespace nvcuda;

#define N_NODES  100000
#define N_EDGES  3200000
#define N_GRAPHS 512
#define F_IN     128
#define F_HID    64
#define F_OUT    10

#define SCAN_B   512
#define NBLK     ((N_NODES + SCAN_B - 1) / SCAN_B)   // 196

#define TG_GRID  1184

// ---------------- scratch (device globals: no allocation allowed) ----------
__device__ int      g_count [N_NODES];
__device__ int      g_cursor[N_NODES];
__device__ int      g_off   [N_NODES + 1];
__device__ int      g_bsum  [NBLK];
__device__ int      g_boff  [NBLK];
__device__ int      g_src   [N_EDGES];
__device__ float    g_dinv  [N_NODES];
__device__ __half2  g_x0h   [N_NODES * 64];   // X0 pre-converted to fp16
__device__ uint32_t g_q8    [N_NODES * 16];   // messages, e4m3 fp8 (64B/row)
__device__ __half2  g_xh1   [N_NODES * 32];   // activations, fp16
__device__ __half2  g_xh2   [N_NODES * 32];
__device__ __half2  g_xh3   [N_NODES * 32];
__device__ int      g_start [N_GRAPHS + 1];
__device__ float    g_pool  [N_GRAPHS * 3 * F_HID];

// ---------------- fp8 helpers ------------------------------------------------
__device__ __forceinline__ uint32_t pack_fp8x4(float a, float b, float c,
                                               float d) {
    __nv_fp8x2_storage_t lo =
        __nv_cvt_float2_to_fp8x2(make_float2(a, b), __NV_SATFINITE, __NV_E4M3);
    __nv_fp8x2_storage_t hi =
        __nv_cvt_float2_to_fp8x2(make_float2(c, d), __NV_SATFINITE, __NV_E4M3);
    return (uint32_t)lo | ((uint32_t)hi << 16);
}
// dequant-accumulate in half2: 2 cvt + 2 HADD2 per 4 features
__device__ __forceinline__ void dqh(__half2& s01, __half2& s23, uint32_t v) {
    __half2_raw h0 = __nv_cvt_fp8x2_to_halfraw2(
        (__nv_fp8x2_storage_t)(v & 0xFFFF), __NV_E4M3);
    __half2_raw h1 = __nv_cvt_fp8x2_to_halfraw2(
        (__nv_fp8x2_storage_t)(v >> 16), __NV_E4M3);
    s01 = __hadd2(s01, *(__half2*)&h0);
    s23 = __hadd2(s23, *(__half2*)&h1);
}
__device__ __forceinline__ void flushh(float& ax, float& ay, float& az,
                                       float& aw, __half2& s01, __half2& s23) {
    float2 p = __half22float2(s01);
    float2 q = __half22float2(s23);
    ax += p.x; ay += p.y; az += q.x; aw += q.y;
    s01 = __float2half2_rn(0.f);
    s23 = __float2half2_rn(0.f);
}

// ---------------- prep -------------------------------------------------------
__global__ void init_kernel(const float* __restrict__ X0) {
    int i = blockIdx.x * blockDim.x + threadIdx.x;
    int stride = gridDim.x * blockDim.x;
    for (int k = i; k < N_NODES; k += stride) g_count[k] = 0;
    for (int k = i; k <= N_GRAPHS; k += stride) g_start[k] = -1;
    const float4* s = (const float4*)X0;
    uint2* d = (uint2*)g_x0h;
    for (int k = i; k < N_NODES * F_IN / 4; k += stride) {
        float4 v = __ldg(&s[k]);
        __half2 a = __floats2half2_rn(v.x, v.y);
        __half2 b = __floats2half2_rn(v.z, v.w);
        d[k] = make_uint2(*(uint32_t*)&a, *(uint32_t*)&b);
    }
}

__global__ void count_kernel(const int* __restrict__ ei) {
    int t = blockIdx.x * blockDim.x + threadIdx.x;
    if (t >= N_EDGES / 4) return;
    int4 c = __ldg(&((const int4*)(ei + N_EDGES))[t]);
    if ((unsigned)c.x < N_NODES) atomicAdd(&g_count[c.x], 1);
    if ((unsigned)c.y < N_NODES) atomicAdd(&g_count[c.y], 1);
    if ((unsigned)c.z < N_NODES) atomicAdd(&g_count[c.z], 1);
    if ((unsigned)c.w < N_NODES) atomicAdd(&g_count[c.w], 1);
}

__global__ void scan1_kernel() {
    __shared__ int s[SCAN_B];
    int t = threadIdx.x;
    int i = blockIdx.x * SCAN_B + t;
    int v = (i < N_NODES) ? g_count[i] : 0;
    if (i < N_NODES) g_dinv[i] = (v > 0) ? rsqrtf((float)v) : 0.0f;
    s[t] = v; __syncthreads();
    int x = v;
    for (int o = 1; o < SCAN_B; o <<= 1) {
        int y = (t >= o) ? s[t - o] : 0;
        __syncthreads();
        x += y; s[t] = x;
        __syncthreads();
    }
    if (i < N_NODES) g_off[i] = x - v;
    if (t == SCAN_B - 1) g_bsum[blockIdx.x] = x;
}

__global__ void scan2_kernel() {
    __shared__ int s[256];
    int t = threadIdx.x;
    int v = (t < NBLK) ? g_bsum[t] : 0;
    s[t] = v; __syncthreads();
    int x = v;
    for (int o = 1; o < 256; o <<= 1) {
        int y = (t >= o) ? s[t - o] : 0;
        __syncthreads();
        x += y; s[t] = x;
        __syncthreads();
    }
    if (t < NBLK) g_boff[t] = x - v;
}

__global__ void scan3_kernel() {
    int i = blockIdx.x * blockDim.x + threadIdx.x;
    if (i < N_NODES) {
        int off = g_off[i] + g_boff[i / SCAN_B];
        g_off[i] = off;
        g_cursor[i] = off;                 // prime scatter cursors
    }
    if (i == 0) g_off[N_NODES] = N_EDGES;
}

__global__ void scatter_kernel(const int* __restrict__ ei) {
    int t = blockIdx.x * blockDim.x + threadIdx.x;
    if (t >= N_EDGES / 4) return;
    int4 r = __ldg(&((const int4*)ei)[t]);
    int4 c = __ldg(&((const int4*)(ei + N_EDGES))[t]);
    if ((unsigned)c.x < N_NODES) g_src[atomicAdd(&g_cursor[c.x], 1)] = r.x;
    if ((unsigned)c.y < N_NODES) g_src[atomicAdd(&g_cursor[c.y], 1)] = r.y;
    if ((unsigned)c.z < N_NODES) g_src[atomicAdd(&g_cursor[c.z], 1)] = r.z;
    if ((unsigned)c.w < N_NODES) g_src[atomicAdd(&g_cursor[c.w], 1)] = r.w;
}

// ------- GEMM via wmma (R15/R16) with fp8 message output --------------------
template <int K>
__global__ __launch_bounds__(128) void tgemm_kernel(
        const float* __restrict__ W, int src) {
    constexpr int KP   = K + 8;
    constexpr int U4PT = (64 * K / 8) / 128;
    constexpr int XB   = 64 * KP * 2;
    constexpr int BUF  = (XB > 16384) ? XB : 16384;
    __shared__ __half        sW[K * 72];
    __shared__ unsigned char sbuf[BUF];
    __half* sXh  = (__half*)sbuf;
    float*  sOut = (float*)sbuf;

    int tid = threadIdx.x, warp = tid >> 5;

    for (int i = tid; i < K * 64; i += 128) {
        int k = i >> 6, n = i & 63;
        sW[k * 72 + n] = __float2half_rn(__ldg(&W[i]));
    }

    const uint4* Xin = (const uint4*)((src == 0) ? g_x0h
                                    : (src == 1) ? g_xh1 : g_xh2);
    const int ROW_U4 = K / 8;
    const int TOT_U4 = N_NODES * ROW_U4;
    const int NT = (N_NODES + 63) / 64;
    for (int tile = blockIdx.x; tile < NT; tile += gridDim.x) {
        int node0 = tile * 64;
        __syncthreads();

        uint4 r[U4PT];
        int base = node0 * ROW_U4;
#pragma unroll
        for (int j = 0; j < U4PT; j++) {
            int gi = base + tid + j * 128;
            r[j] = (gi < TOT_U4) ? __ldg(&Xin[gi]) : make_uint4(0, 0, 0, 0);
        }
#pragma unroll
        for (int j = 0; j < U4PT; j++) {
            int i = tid + j * 128;
            int row = i / ROW_U4, c16 = i % ROW_U4;
            *(uint4*)&sXh[row * KP + c16 * 8] = r[j];
        }
        __syncthreads();

        wmma::fragment<wmma::accumulator, 16, 16, 16, float> acc[4];
#pragma unroll
        for (int j = 0; j < 4; j++) wmma::fill_fragment(acc[j], 0.0f);
        wmma::fragment<wmma::matrix_a, 16, 16, 16, __half, wmma::row_major> a;
        wmma::fragment<wmma::matrix_b, 16, 16, 16, __half, wmma::row_major> b;
        int rowBase = warp * 16;
#pragma unroll
        for (int ks = 0; ks < K / 16; ks++) {
            wmma::load_matrix_sync(a, &sXh[rowBase * KP + ks * 16], KP);
#pragma unroll
            for (int j = 0; j < 4; j++) {
                wmma::load_matrix_sync(b, &sW[ks * 16 * 72 + j * 16], 72);
                wmma::mma_sync(acc[j], a, b, acc[j]);
            }
        }
        __syncthreads();
#pragma unroll
        for (int j = 0; j < 4; j++)
            wmma::store_matrix_sync(&sOut[rowBase * 64 + j * 16], acc[j], 64,
                                    wmma::mem_row_major);
        __syncthreads();

        int row = tid >> 1, hsel = tid & 1;
        int node = node0 + row;
        if (node < N_NODES) {
            float dv = g_dinv[node];
            const float* p = &sOut[row * 64 + hsel * 32];
            uint4* dst = (uint4*)&g_q8[(size_t)node * 16 + hsel * 8];
#pragma unroll
            for (int q = 0; q < 2; q++) {
                uint4 o;
                o.x = pack_fp8x4(p[q*16+ 0]*dv, p[q*16+ 1]*dv,
                                 p[q*16+ 2]*dv, p[q*16+ 3]*dv);
                o.y = pack_fp8x4(p[q*16+ 4]*dv, p[q*16+ 5]*dv,
                                 p[q*16+ 6]*dv, p[q*16+ 7]*dv);
                o.z = pack_fp8x4(p[q*16+ 8]*dv, p[q*16+ 9]*dv,
                                 p[q*16+10]*dv, p[q*16+11]*dv);
                o.w = pack_fp8x4(p[q*16+12]*dv, p[q*16+13]*dv,
                                 p[q*16+14]*dv, p[q*16+15]*dv);
                dst[q] = o;
            }
        }
    }
}

// ------- aggregate: fp8 gather + half2 accumulation --------------------------
// lane = (half, fl): fl covers features 4fl..4fl+3 via one uint32 (4 fp8).
// 16-edge main loop: 4 idx + 8 data loads front-batched (MLP 8), HADD2
// accumulation, fp32 flush once per chunk.
__global__ void aggregate_kernel(const float* __restrict__ b, int dst) {
    int node = blockIdx.x * 8 + (threadIdx.x >> 5);
    int lane = threadIdx.x & 31;
    if (node >= N_NODES) return;
    int half = lane >> 4;
    int fl   = lane & 15;

    const uint32_t* Q = g_q8;                // row = 16 uint32 = 64B
    int beg = g_off[node], end = g_off[node + 1];
    float ax = 0.f, ay = 0.f, az = 0.f, aw = 0.f;
    __half2 s01 = __float2half2_rn(0.f), s23 = __float2half2_rn(0.f);

    int e = beg;
    for (; e < end && (e & 3); e++) {        // align to 16B
        if (half == 0) dqh(s01, s23, __ldg(&Q[__ldg(&g_src[e]) * 16 + fl]));
    }
    const int4* s4 = (const int4*)g_src;
    for (; e + 16 <= end; e += 16) {
        int b4 = e >> 2;
        int4 i0 = __ldg(&s4[b4 + 0]);
        int4 i1 = __ldg(&s4[b4 + 1]);
        int4 i2 = __ldg(&s4[b4 + 2]);
        int4 i3 = __ldg(&s4[b4 + 3]);
        int sA = half ? i0.y : i0.x, sB = half ? i0.w : i0.z;
        int sC = half ? i1.y : i1.x, sD = half ? i1.w : i1.z;
        int sE = half ? i2.y : i2.x, sF = half ? i2.w : i2.z;
        int sG = half ? i3.y : i3.x, sH = half ? i3.w : i3.z;
        uint32_t vA = __ldg(&Q[sA * 16 + fl]);
        uint32_t vB = __ldg(&Q[sB * 16 + fl]);
        uint32_t vC = __ldg(&Q[sC * 16 + fl]);
        uint32_t vD = __ldg(&Q[sD * 16 + fl]);
        uint32_t vE = __ldg(&Q[sE * 16 + fl]);
        uint32_t vF = __ldg(&Q[sF * 16 + fl]);
        uint32_t vG = __ldg(&Q[sG * 16 + fl]);
        uint32_t vH = __ldg(&Q[sH * 16 + fl]);
        dqh(s01, s23, vA); dqh(s01, s23, vB);
        dqh(s01, s23, vC); dqh(s01, s23, vD);
        dqh(s01, s23, vE); dqh(s01, s23, vF);
        dqh(s01, s23, vG); dqh(s01, s23, vH);
        flushh(ax, ay, az, aw, s01, s23);
    }
    if (e + 8 <= end) {
        int b4 = e >> 2;
        int4 i0 = __ldg(&s4[b4 + 0]);
        int4 i1 = __ldg(&s4[b4 + 1]);
        int sA = half ? i0.y : i0.x, sB = half ? i0.w : i0.z;
        int sC = half ? i1.y : i1.x, sD = half ? i1.w : i1.z;
        uint32_t vA = __ldg(&Q[sA * 16 + fl]);
        uint32_t vB = __ldg(&Q[sB * 16 + fl]);
        uint32_t vC = __ldg(&Q[sC * 16 + fl]);
        uint32_t vD = __ldg(&Q[sD * 16 + fl]);
        dqh(s01, s23, vA); dqh(s01, s23, vB);
        dqh(s01, s23, vC); dqh(s01, s23, vD);
        e += 8;
    }
    if (e + 4 <= end) {
        int4 i0 = __ldg(&s4[e >> 2]);
        int sA = half ? i0.y : i0.x, sB = half ? i0.w : i0.z;
        uint32_t vA = __ldg(&Q[sA * 16 + fl]);
        uint32_t vB = __ldg(&Q[sB * 16 + fl]);
        dqh(s01, s23, vA); dqh(s01, s23, vB);
        e += 4;
    }
    for (; e < end; e++) {
        if (half == 0) dqh(s01, s23, __ldg(&Q[__ldg(&g_src[e]) * 16 + fl]));
    }
    flushh(ax, ay, az, aw, s01, s23);

    ax += __shfl_xor_sync(0xffffffff, ax, 16);
    ay += __shfl_xor_sync(0xffffffff, ay, 16);
    az += __shfl_xor_sync(0xffffffff, az, 16);
    aw += __shfl_xor_sync(0xffffffff, aw, 16);

    if (half == 0) {
        float di = g_dinv[node];
        float4 bb = __ldg(&((const float4*)b)[fl]);
        float vx = fmaxf(fmaf(ax, di, bb.x), 0.0f);
        float vy = fmaxf(fmaf(ay, di, bb.y), 0.0f);
        float vz = fmaxf(fmaf(az, di, bb.z), 0.0f);
        float vw = fmaxf(fmaf(aw, di, bb.w), 0.0f);
        __half2 h0 = __floats2half2_rn(vx, vy);
        __half2 h1 = __floats2half2_rn(vz, vw);
        float2 st;
        *(__half2*)&st.x = h0;
        *(__half2*)&st.y = h1;
        float2* out = (float2*)((dst == 1) ? g_xh1 : (dst == 2) ? g_xh2 : g_xh3);
        out[node * 16 + fl] = st;
    }
}

// ---------------- pooling over sorted batch ----------------------------------
__global__ void start_set_kernel(const int* __restrict__ batch) {
    int i = blockIdx.x * blockDim.x + threadIdx.x;
    if (i >= N_NODES) return;
    int bcur = batch[i];
    if ((unsigned)bcur >= N_GRAPHS) return;
    if (i == 0 || batch[i - 1] != bcur) g_start[bcur] = i;
    if (i == 0) g_start[N_GRAPHS] = N_NODES;
}

__global__ void start_fix_kernel() {
    __shared__ int s[N_GRAPHS + 1];
    int t = threadIdx.x;
    for (int k = t; k <= N_GRAPHS; k += blockDim.x) s[k] = g_start[k];
    __syncthreads();
    if (t == 0) {
        int nxt = s[N_GRAPHS];
        for (int g = N_GRAPHS - 1; g >= 0; --g) {
            if (s[g] < 0) s[g] = nxt;
            nxt = s[g];
        }
    }
    __syncthreads();
    for (int k = t; k <= N_GRAPHS; k += blockDim.x) g_start[k] = s[k];
}

__global__ void pool_kernel() {
    int g = blockIdx.x;
    int t = threadIdx.x;                  // 0..95
    int layer = t >> 5, p = t & 31;
    int beg = g_start[g], end = g_start[g + 1];
    const __half2* src = (layer == 0) ? g_xh1 : (layer == 1) ? g_xh2 : g_xh3;
    float x0 = 0.f, y0 = 0.f, x1 = 0.f, y1 = 0.f;
    float x2 = 0.f, y2 = 0.f, x3 = 0.f, y3 = 0.f;
    int n = beg;
    for (; n + 4 <= end; n += 4) {
        float2 v0 = __half22float2(src[(n + 0) * 32 + p]);
        float2 v1 = __half22float2(src[(n + 1) * 32 + p]);
        float2 v2 = __half22float2(src[(n + 2) * 32 + p]);
        float2 v3 = __half22float2(src[(n + 3) * 32 + p]);
        x0 += v0.x; y0 += v0.y;  x1 += v1.x; y1 += v1.y;
        x2 += v2.x; y2 += v2.y;  x3 += v3.x; y3 += v3.y;
    }
    for (; n < end; n++) {
        float2 v = __half22float2(src[n * 32 + p]);
        x0 += v.x; y0 += v.y;
    }
    float inv = 1.0f / (float)max(end - beg, 1);
    float2* dst = (float2*)&g_pool[g * (3 * F_HID)];
    dst[layer * 32 + p] = make_float2(((x0 + x1) + (x2 + x3)) * inv,
                                      ((y0 + y1) + (y2 + y3)) * inv);
}

__global__ void final_kernel(const float* __restrict__ Wf,
                             const float* __restrict__ bf,
                             float* __restrict__ out) {
    int g = blockIdx.x;
    int j = threadIdx.x;
    float logit = __int_as_float(0xff800000);
    if (j < F_OUT) {
        float acc = bf[j];
        const float* p = g_pool + g * (3 * F_HID);
#pragma unroll 16
        for (int k = 0; k < 3 * F_HID; k++)
            acc = fmaf(p[k], Wf[k * F_OUT + j], acc);
        logit = acc;
    }
    float m = logit;
    for (int o = 16; o; o >>= 1) m = fmaxf(m, __shfl_xor_sync(0xffffffff, m, o));
    float ex = (j < F_OUT) ? expf(logit - m) : 0.0f;
    float s = ex;
    for (int o = 16; o; o >>= 1) s += __shfl_xor_sync(0xffffffff, s, o);
    if (j < F_OUT) out[g * F_OUT + j] = ex / s;
}

// ---------------- launch -----------------------------------------------------
// gemm1 stays 4th: the fixed ncu window profiles launch #4.
extern "C" void kernel_launch(void* const* d_in, const int* in_sizes, int n_in,
                              void* d_out, int out_size) {
    const float* X0    = (const float*)d_in[0];
    const int*   ei    = (const int*)d_in[1];    // int32 (JAX x64 disabled)
    const int*   batch = (const int*)d_in[2];
    const float* W1    = (const float*)d_in[3];
    const float* b1    = (const float*)d_in[4];
    const float* W2    = (const float*)d_in[5];
    const float* b2    = (const float*)d_in[6];
    const float* W3    = (const float*)d_in[7];
    const float* b3    = (const float*)d_in[8];
    const float* Wf    = (const float*)d_in[9];
    const float* bf    = (const float*)d_in[10];
    float* out = (float*)d_out;

    const int TB = 256;
    const int gridE4 = (N_EDGES / 4 + TB - 1) / TB;
    const int gridN  = (N_NODES + TB - 1) / TB;
    const int grid8  = (N_NODES + 7) / 8;

    init_kernel<<<2048, TB>>>(X0);                       // 1 (+X0 fp16 convert)
    count_kernel<<<gridE4, TB>>>(ei);                    // 2
    scan1_kernel<<<NBLK, SCAN_B>>>();                    // 3 (dinv ready)
    tgemm_kernel<F_IN><<<TG_GRID, 128>>>(W1, 0);         // 4 <- profiled
    scan2_kernel<<<1, 256>>>();                          // 5
    scan3_kernel<<<gridN, TB>>>();                       // 6 (primes cursor)
    scatter_kernel<<<gridE4, TB>>>(ei);                  // 7
    start_set_kernel<<<gridN, TB>>>(batch);              // 8
    start_fix_kernel<<<1, 256>>>();                      // 9

    aggregate_kernel<<<grid8, TB>>>(b1, 1);              // 10
    tgemm_kernel<F_HID><<<TG_GRID, 128>>>(W2, 1);
    aggregate_kernel<<<grid8, TB>>>(b2, 2);
    tgemm_kernel<F_HID><<<TG_GRID, 128>>>(W3, 2);
    aggregate_kernel<<<grid8, TB>>>(b3, 3);

    pool_kernel<<<N_GRAPHS, 96>>>();
    final_kernel<<<N_GRAPHS, 32>>>(Wf, bf, out);
}